// round 4
// baseline (speedup 1.0000x reference)
#include <cuda_runtime.h>
#include <math.h>

#define KDIM 8192
#define BDIM 512
#define PDIM 4096
#define KSUB (KDIM / 4)          // 2048 k's per k_accum CTA

// Scratch (allocation-free rule: __device__ globals)
__device__ float g_Apart[BDIM * 4 * 10]; // per-CTA partial A (10 uniques)
__device__ float g_M[BDIM * 9];          // per-batch (rm_pred - rm_gt)
__device__ float g_part[2048];           // per-block partial sums for phase 3
__device__ unsigned int g_bcnt[BDIM];    // per-batch CTA-done counters (self-reset)
__device__ unsigned int g_cnt;           // global last-block counter (self-reset)

__device__ __forceinline__ float warpSum(float v) {
    #pragma unroll
    for (int o = 16; o; o >>= 1) v += __shfl_xor_sync(0xffffffffu, v, o);
    return v;
}

// FMA/ALU-pipe exp (no MUFU). |x| <= ~20, rel err ~1.5e-7.
__device__ __forceinline__ float fexp(float x) {
    float t  = x * 1.4426950408889634f;
    float fn = t + 12582912.0f;
    int   n  = __float_as_int(fn) - 0x4B400000;
    float r  = t - (fn - 12582912.0f);
    float p = 1.5403530393e-4f;
    p = fmaf(p, r, 1.3333558146e-3f);
    p = fmaf(p, r, 9.6181291076e-3f);
    p = fmaf(p, r, 5.5504108665e-2f);
    p = fmaf(p, r, 2.4022650696e-1f);
    p = fmaf(p, r, 6.9314718056e-1f);
    p = fmaf(p, r, 1.0f);
    return __int_as_float(__float_as_int(p) + (n << 23));
}

// FMA/ALU-pipe sqrt: magic rsqrt + 2 Newton iters, then c * rsqrt(c).
__device__ __forceinline__ float fsqrt_fma(float c) {
    float y = __int_as_float(0x5f3759df - (__float_as_int(c) >> 1));
    float h = 0.5f * c;
    y = y * fmaf(-h * y, y, 1.5f);
    y = y * fmaf(-h * y, y, 1.5f);
    return c * y;
}

__device__ __forceinline__ void quat2mat(const float qv[4], float mm[9]) {
    float r = qv[0], i = qv[1], j = qv[2], k = qv[3];
    float two_s = __fdividef(2.0f, r * r + i * i + j * j + k * k);
    mm[0] = 1.0f - two_s * (j * j + k * k);
    mm[1] = two_s * (i * j - k * r);
    mm[2] = two_s * (i * k + j * r);
    mm[3] = two_s * (i * j + k * r);
    mm[4] = 1.0f - two_s * (i * i + k * k);
    mm[5] = two_s * (j * k - i * r);
    mm[6] = two_s * (i * k - j * r);
    mm[7] = two_s * (j * k + i * r);
    mm[8] = 1.0f - two_s * (i * i + j * j);
}

// ---------------------------------------------------------------------------
// Kernel 1: 4 CTAs per batch stream quarter-rows, accumulate partial
// A = sum_k e^{s_k} q_k q_k^T (10 uniques). Last-done CTA of each batch sums
// the 4 partials, runs Jacobi eig + quat->mat diff, writes g_M -- overlapping
// with other batches' streaming.
// ---------------------------------------------------------------------------
__global__ __launch_bounds__(256) void k_accum(const float* __restrict__ s,
                                               const float* __restrict__ q,
                                               const float* __restrict__ gt) {
    const int blk = blockIdx.x;
    const int b = blk >> 2;
    const int sub = blk & 3;
    const int t = threadIdx.x;

    __shared__ float red[80];

    const float4* __restrict__ s4 =
        (const float4*)(s + (size_t)b * KDIM + (size_t)sub * KSUB);
    const float4* __restrict__ q4 =
        (const float4*)(q + ((size_t)b * KDIM + (size_t)sub * KSUB) * 4);

    float a0 = 0.f, a1 = 0.f, a2 = 0.f, a3 = 0.f, a4 = 0.f;
    float a5 = 0.f, a6 = 0.f, a7 = 0.f, a8 = 0.f, a9 = 0.f;

    #pragma unroll
    for (int i = 0; i < KSUB / 4 / 256; i++) {     // 2 iters; 4 k's per iter
        int idx = t + i * 256;
        float4 sv = s4[idx];
        float4 qa = q4[4 * idx + 0];
        float4 qb = q4[4 * idx + 1];
        float4 qc = q4[4 * idx + 2];
        float4 qd = q4[4 * idx + 3];
        float w0 = fexp(sv.x), w1 = fexp(sv.y), w2 = fexp(sv.z), w3 = fexp(sv.w);
        {
            float wr = w0 * qa.x, wi = w0 * qa.y, wj = w0 * qa.z, wk = w0 * qa.w;
            a0 += wr * qa.x; a1 += wr * qa.y; a2 += wr * qa.z; a3 += wr * qa.w;
            a4 += wi * qa.y; a5 += wi * qa.z; a6 += wi * qa.w;
            a7 += wj * qa.z; a8 += wj * qa.w; a9 += wk * qa.w;
        }
        {
            float wr = w1 * qb.x, wi = w1 * qb.y, wj = w1 * qb.z, wk = w1 * qb.w;
            a0 += wr * qb.x; a1 += wr * qb.y; a2 += wr * qb.z; a3 += wr * qb.w;
            a4 += wi * qb.y; a5 += wi * qb.z; a6 += wi * qb.w;
            a7 += wj * qb.z; a8 += wj * qb.w; a9 += wk * qb.w;
        }
        {
            float wr = w2 * qc.x, wi = w2 * qc.y, wj = w2 * qc.z, wk = w2 * qc.w;
            a0 += wr * qc.x; a1 += wr * qc.y; a2 += wr * qc.z; a3 += wr * qc.w;
            a4 += wi * qc.y; a5 += wi * qc.z; a6 += wi * qc.w;
            a7 += wj * qc.z; a8 += wj * qc.w; a9 += wk * qc.w;
        }
        {
            float wr = w3 * qd.x, wi = w3 * qd.y, wj = w3 * qd.z, wk = w3 * qd.w;
            a0 += wr * qd.x; a1 += wr * qd.y; a2 += wr * qd.z; a3 += wr * qd.w;
            a4 += wi * qd.y; a5 += wi * qd.z; a6 += wi * qd.w;
            a7 += wj * qd.z; a8 += wj * qd.w; a9 += wk * qd.w;
        }
    }

    // Deterministic block reduction of the 10 accumulators
    float acc[10] = {a0, a1, a2, a3, a4, a5, a6, a7, a8, a9};
    #pragma unroll
    for (int i = 0; i < 10; i++) acc[i] = warpSum(acc[i]);
    const int w = t >> 5, l = t & 31;
    if (l == 0) {
        #pragma unroll
        for (int i = 0; i < 10; i++) red[w * 10 + i] = acc[i];
    }
    __syncthreads();

    if (t == 0) {
        // Sum 8 warps -> this CTA's partial A; publish.
        #pragma unroll
        for (int i = 0; i < 10; i++) {
            float sA = 0.f;
            #pragma unroll
            for (int w2 = 0; w2 < 8; w2++) sA += red[w2 * 10 + i];
            g_Apart[(size_t)blk * 10 + i] = sA;
        }
        __threadfence();
        unsigned int prev = atomicAdd(&g_bcnt[b], 1u);
        if (prev == 3u) {
            g_bcnt[b] = 0u;   // reset for next graph replay
            // Deterministic fixed-order sum of the 4 partials.
            float A[10];
            #pragma unroll
            for (int i = 0; i < 10; i++) {
                float sA = 0.f;
                #pragma unroll
                for (int j = 0; j < 4; j++)
                    sA += g_Apart[((size_t)b * 4 + j) * 10 + i];
                A[i] = sA;
            }

            float a[4][4], v[4][4];
            a[0][0] = A[0];
            a[0][1] = a[1][0] = A[1];
            a[0][2] = a[2][0] = A[2];
            a[0][3] = a[3][0] = A[3];
            a[1][1] = A[4];
            a[1][2] = a[2][1] = A[5];
            a[1][3] = a[3][1] = A[6];
            a[2][2] = A[7];
            a[2][3] = a[3][2] = A[8];
            a[3][3] = A[9];
            #pragma unroll
            for (int i = 0; i < 4; i++)
                #pragma unroll
                for (int j = 0; j < 4; j++) v[i][j] = (i == j) ? 1.0f : 0.0f;

            const int PP[6] = {0, 0, 0, 1, 1, 2};
            const int QQ[6] = {1, 2, 3, 2, 3, 3};

            for (int sweep = 0; sweep < 6; sweep++) {
                #pragma unroll
                for (int pair = 0; pair < 6; pair++) {
                    int p = PP[pair], qi = QQ[pair];
                    float apq = a[p][qi];
                    if (fabsf(apq) > 1e-30f) {
                        float theta = __fdividef(a[qi][qi] - a[p][p], 2.0f * apq);
                        float tt = __fdividef(1.0f, fabsf(theta) + sqrtf(theta * theta + 1.0f));
                        if (theta < 0.0f) tt = -tt;
                        float c = rsqrtf(tt * tt + 1.0f);
                        float sn = tt * c;
                        float app = a[p][p], aqq = a[qi][qi];
                        a[p][p] = app - tt * apq;
                        a[qi][qi] = aqq + tt * apq;
                        a[p][qi] = a[qi][p] = 0.0f;
                        #pragma unroll
                        for (int r = 0; r < 4; r++) {
                            if (r != p && r != qi) {
                                float arp = a[r][p], arq = a[r][qi];
                                a[r][p] = a[p][r] = c * arp - sn * arq;
                                a[r][qi] = a[qi][r] = sn * arp + c * arq;
                            }
                        }
                        #pragma unroll
                        for (int r = 0; r < 4; r++) {
                            float vrp = v[r][p], vrq = v[r][qi];
                            v[r][p] = c * vrp - sn * vrq;
                            v[r][qi] = sn * vrp + c * vrq;
                        }
                    }
                }
            }

            int best = 0;
            float bv = a[0][0];
            #pragma unroll
            for (int i = 1; i < 4; i++)
                if (a[i][i] > bv) { bv = a[i][i]; best = i; }

            float qp[4] = {v[0][best], v[1][best], v[2][best], v[3][best]};
            float mp[9], mg[9];
            quat2mat(qp, mp);
            float qg[4] = {gt[b * 4 + 0], gt[b * 4 + 1], gt[b * 4 + 2], gt[b * 4 + 3]};
            quat2mat(qg, mg);
            #pragma unroll
            for (int i = 0; i < 9; i++) g_M[b * 9 + i] = mp[i] - mg[i];
        }
    }
}

// ---------------------------------------------------------------------------
// Kernel 2: per-point || p . (rm_pred - rm_gt) ||, sqrt on FMA pipe.
// 4 CTAs per batch (grid 2048), 4 points/thread (3x LDG.128). Last-finished
// block does the deterministic final reduction over 2048 partials.
// ---------------------------------------------------------------------------
__global__ __launch_bounds__(256) void k_point(const float* __restrict__ point,
                                               float* __restrict__ out) {
    const int blk = blockIdx.x;
    const int b = blk >> 2;
    const int sub = blk & 3;
    const int t = threadIdx.x;

    __shared__ float Ms[9];
    __shared__ float red[8];
    __shared__ int isLast;
    if (t < 9) Ms[t] = g_M[b * 9 + t];

    const float4* __restrict__ p4 =
        (const float4*)(point + ((size_t)b * PDIM + (size_t)sub * 1024) * 3);
    float4 v0 = p4[3 * t + 0];
    float4 v1 = p4[3 * t + 1];
    float4 v2 = p4[3 * t + 2];
    __syncthreads();
    const float M0 = Ms[0], M1 = Ms[1], M2 = Ms[2];
    const float M3 = Ms[3], M4 = Ms[4], M5 = Ms[5];
    const float M6 = Ms[6], M7 = Ms[7], M8 = Ms[8];

    float px[4] = {v0.x, v0.w, v1.z, v2.y};
    float py[4] = {v0.y, v1.x, v1.w, v2.z};
    float pz[4] = {v0.z, v1.y, v2.x, v2.w};

    float acc = 0.f;
    #pragma unroll
    for (int r = 0; r < 4; r++) {
        float x = px[r], y = py[r], z = pz[r];
        float dx = x * M0 + y * M3 + z * M6;
        float dy = x * M1 + y * M4 + z * M7;
        float dz = x * M2 + y * M5 + z * M8;
        acc += fsqrt_fma(dx * dx + dy * dy + dz * dz);
    }
    acc = warpSum(acc);
    if ((t & 31) == 0) red[t >> 5] = acc;
    __syncthreads();
    if (t < 32) {
        float x = (t < 8) ? red[t] : 0.f;
        x = warpSum(x);
        if (t == 0) g_part[blk] = x;
    }

    // Last-block-done final reduction (deterministic fixed-order sum).
    if (t == 0) {
        __threadfence();
        unsigned int prev = atomicAdd(&g_cnt, 1u);
        isLast = (prev == 2047u);
    }
    __syncthreads();
    if (isLast) {
        float sfin = 0.f;
        #pragma unroll
        for (int i = 0; i < 8; i++) sfin += g_part[t + i * 256];
        sfin = warpSum(sfin);
        if ((t & 31) == 0) red[t >> 5] = sfin;
        __syncthreads();
        if (t < 32) {
            float x = (t < 8) ? red[t] : 0.f;
            x = warpSum(x);
            if (t == 0) {
                out[0] = x * (1.0f / ((float)BDIM * (float)PDIM));
                g_cnt = 0u;   // reset for next graph replay
            }
        }
    }
}

extern "C" void kernel_launch(void* const* d_in, const int* in_sizes, int n_in,
                              void* d_out, int out_size) {
    const float* s     = (const float*)d_in[0];  // softEncodePred (B,K)
    const float* q     = (const float*)d_in[1];  // oriHistogramMap (B,K,4)
    const float* gt    = (const float*)d_in[2];  // gt (B,4)
    const float* point = (const float*)d_in[3];  // point (B,P,3)
    float* out = (float*)d_out;

    k_accum<<<4 * BDIM, 256>>>(s, q, gt);
    k_point<<<4 * BDIM, 256>>>(point, out);
}

// round 5
// speedup vs baseline: 1.2435x; 1.2435x over previous
#include <cuda_runtime.h>
#include <math.h>

#define KDIM 8192
#define BDIM 512
#define PDIM 4096

// Scratch (allocation-free rule: __device__ globals)
__device__ float g_M[BDIM * 9];      // per-batch (rm_pred - rm_gt)
__device__ float g_part[BDIM];       // per-block partial sums for phase 3
__device__ unsigned int g_cnt;       // last-block-done counter (self-reset)

__device__ __forceinline__ float warpSum(float v) {
    #pragma unroll
    for (int o = 16; o; o >>= 1) v += __shfl_xor_sync(0xffffffffu, v, o);
    return v;
}

// cp.async helpers (16B, cache-global)
__device__ __forceinline__ void cpa16(unsigned dst, const void* src) {
    asm volatile("cp.async.cg.shared.global [%0], [%1], 16;" :: "r"(dst), "l"(src));
}
__device__ __forceinline__ void cpa_commit() {
    asm volatile("cp.async.commit_group;");
}
template <int N>
__device__ __forceinline__ void cpa_wait() {
    asm volatile("cp.async.wait_group %0;" :: "n"(N));
}
__device__ __forceinline__ unsigned smem_u32(const void* p) {
    return (unsigned)__cvta_generic_to_shared(p);
}

// FMA/ALU-pipe exp (no MUFU). |x| <= ~20, rel err ~1.5e-7.
__device__ __forceinline__ float fexp(float x) {
    float t  = x * 1.4426950408889634f;
    float fn = t + 12582912.0f;
    int   n  = __float_as_int(fn) - 0x4B400000;
    float r  = t - (fn - 12582912.0f);
    float p = 1.5403530393e-4f;
    p = fmaf(p, r, 1.3333558146e-3f);
    p = fmaf(p, r, 9.6181291076e-3f);
    p = fmaf(p, r, 5.5504108665e-2f);
    p = fmaf(p, r, 2.4022650696e-1f);
    p = fmaf(p, r, 6.9314718056e-1f);
    p = fmaf(p, r, 1.0f);
    return __int_as_float(__float_as_int(p) + (n << 23));
}

// FMA/ALU-pipe sqrt: magic rsqrt + 2 Newton iters, then c * rsqrt(c).
__device__ __forceinline__ float fsqrt_fma(float c) {
    float y = __int_as_float(0x5f3759df - (__float_as_int(c) >> 1));
    float h = 0.5f * c;
    y = y * fmaf(-h * y, y, 1.5f);
    y = y * fmaf(-h * y, y, 1.5f);
    return c * y;
}

__device__ __forceinline__ void quat2mat(const float qv[4], float mm[9]) {
    float r = qv[0], i = qv[1], j = qv[2], k = qv[3];
    float two_s = __fdividef(2.0f, r * r + i * i + j * j + k * k);
    mm[0] = 1.0f - two_s * (j * j + k * k);
    mm[1] = two_s * (i * j - k * r);
    mm[2] = two_s * (i * k + j * r);
    mm[3] = two_s * (i * j + k * r);
    mm[4] = 1.0f - two_s * (i * i + k * k);
    mm[5] = two_s * (j * k - i * r);
    mm[6] = two_s * (i * k - j * r);
    mm[7] = two_s * (j * k + i * r);
    mm[8] = 1.0f - two_s * (i * i + j * j);
}

// ---------------------------------------------------------------------------
// Kernel 1: one CTA per batch; 4-stage cp.async pipeline staging s (2 KB) and
// q (8 KB) chunks of 512 k's. Accumulate A = sum_k e^{s_k} q_k q_k^T
// (unnormalized; eigvecs scale-invariant). Inline Jacobi eig in thread 0.
// ---------------------------------------------------------------------------
#define ACHUNK 512
#define ANCH   (KDIM / ACHUNK)     // 16 chunks
#define ANST   4                   // stages

__global__ __launch_bounds__(256) void k_accum(const float* __restrict__ s,
                                               const float* __restrict__ q,
                                               const float* __restrict__ gt) {
    const int b = blockIdx.x;
    const int t = threadIdx.x;

    __shared__ float sq[ANST][ACHUNK * 4];   // 32 KB
    __shared__ float ss[ANST][ACHUNK];       // 8 KB
    __shared__ float red[80];

    const float4* __restrict__ gq = (const float4*)(q + (size_t)b * KDIM * 4);
    const float4* __restrict__ gs = (const float4*)(s + (size_t)b * KDIM);

    // Issue stage: chunk c -> stage st. q chunk = 512 float4; s chunk = 128 float4.
    auto issue = [&](int c, int st) {
        unsigned dq = smem_u32(&sq[st][0]);
        const float4* srcq = gq + c * ACHUNK;
        cpa16(dq + t * 16,        srcq + t);
        cpa16(dq + (t + 256) * 16, srcq + t + 256);
        if (t < 128) {
            unsigned ds = smem_u32(&ss[st][0]);
            cpa16(ds + t * 16, gs + c * (ACHUNK / 4) + t);
        }
        cpa_commit();
    };

    issue(0, 0); issue(1, 1); issue(2, 2);

    float a0 = 0.f, a1 = 0.f, a2 = 0.f, a3 = 0.f, a4 = 0.f;
    float a5 = 0.f, a6 = 0.f, a7 = 0.f, a8 = 0.f, a9 = 0.f;

    #pragma unroll 4
    for (int c = 0; c < ANCH; c++) {
        if (c < ANCH - 2)      cpa_wait<2>();
        else if (c == ANCH - 2) cpa_wait<1>();
        else                    cpa_wait<0>();
        __syncthreads();

        const int st = c & (ANST - 1);
        const float4* q4s = (const float4*)&sq[st][0];
        // 2 k's per thread: t and t+256 (conflict-free 16B-stride LDS)
        float4 qa = q4s[t];
        float4 qb = q4s[t + 256];
        float w0 = fexp(ss[st][t]);
        float w1 = fexp(ss[st][t + 256]);
        {
            float wr = w0 * qa.x, wi = w0 * qa.y, wj = w0 * qa.z, wk = w0 * qa.w;
            a0 += wr * qa.x; a1 += wr * qa.y; a2 += wr * qa.z; a3 += wr * qa.w;
            a4 += wi * qa.y; a5 += wi * qa.z; a6 += wi * qa.w;
            a7 += wj * qa.z; a8 += wj * qa.w; a9 += wk * qa.w;
        }
        {
            float wr = w1 * qb.x, wi = w1 * qb.y, wj = w1 * qb.z, wk = w1 * qb.w;
            a0 += wr * qb.x; a1 += wr * qb.y; a2 += wr * qb.z; a3 += wr * qb.w;
            a4 += wi * qb.y; a5 += wi * qb.z; a6 += wi * qb.w;
            a7 += wj * qb.z; a8 += wj * qb.w; a9 += wk * qb.w;
        }
        __syncthreads();
        if (c + 3 < ANCH) issue(c + 3, (c + 3) & (ANST - 1));
    }

    // Deterministic block reduction of the 10 accumulators
    float acc[10] = {a0, a1, a2, a3, a4, a5, a6, a7, a8, a9};
    #pragma unroll
    for (int i = 0; i < 10; i++) acc[i] = warpSum(acc[i]);
    const int w = t >> 5, l = t & 31;
    if (l == 0) {
        #pragma unroll
        for (int i = 0; i < 10; i++) red[w * 10 + i] = acc[i];
    }
    __syncthreads();

    // Thread 0: finish A, Jacobi eig, quat->mat difference, write g_M.
    if (t == 0) {
        float A[10];
        #pragma unroll
        for (int i = 0; i < 10; i++) {
            float sA = 0.f;
            #pragma unroll
            for (int w2 = 0; w2 < 8; w2++) sA += red[w2 * 10 + i];
            A[i] = sA;
        }

        float a[4][4], v[4][4];
        a[0][0] = A[0];
        a[0][1] = a[1][0] = A[1];
        a[0][2] = a[2][0] = A[2];
        a[0][3] = a[3][0] = A[3];
        a[1][1] = A[4];
        a[1][2] = a[2][1] = A[5];
        a[1][3] = a[3][1] = A[6];
        a[2][2] = A[7];
        a[2][3] = a[3][2] = A[8];
        a[3][3] = A[9];
        #pragma unroll
        for (int i = 0; i < 4; i++)
            #pragma unroll
            for (int j = 0; j < 4; j++) v[i][j] = (i == j) ? 1.0f : 0.0f;

        const int PP[6] = {0, 0, 0, 1, 1, 2};
        const int QQ[6] = {1, 2, 3, 2, 3, 3};

        for (int sweep = 0; sweep < 6; sweep++) {
            #pragma unroll
            for (int pair = 0; pair < 6; pair++) {
                int p = PP[pair], qi = QQ[pair];
                float apq = a[p][qi];
                if (fabsf(apq) > 1e-30f) {
                    float theta = __fdividef(a[qi][qi] - a[p][p], 2.0f * apq);
                    float tt = __fdividef(1.0f, fabsf(theta) + sqrtf(theta * theta + 1.0f));
                    if (theta < 0.0f) tt = -tt;
                    float c = rsqrtf(tt * tt + 1.0f);
                    float sn = tt * c;
                    float app = a[p][p], aqq = a[qi][qi];
                    a[p][p] = app - tt * apq;
                    a[qi][qi] = aqq + tt * apq;
                    a[p][qi] = a[qi][p] = 0.0f;
                    #pragma unroll
                    for (int r = 0; r < 4; r++) {
                        if (r != p && r != qi) {
                            float arp = a[r][p], arq = a[r][qi];
                            a[r][p] = a[p][r] = c * arp - sn * arq;
                            a[r][qi] = a[qi][r] = sn * arp + c * arq;
                        }
                    }
                    #pragma unroll
                    for (int r = 0; r < 4; r++) {
                        float vrp = v[r][p], vrq = v[r][qi];
                        v[r][p] = c * vrp - sn * vrq;
                        v[r][qi] = sn * vrp + c * vrq;
                    }
                }
            }
        }

        int best = 0;
        float bv = a[0][0];
        #pragma unroll
        for (int i = 1; i < 4; i++)
            if (a[i][i] > bv) { bv = a[i][i]; best = i; }

        float qp[4] = {v[0][best], v[1][best], v[2][best], v[3][best]};
        // sign/norm of qp irrelevant: quat2mat divides by |q|^2 and is even in q
        float mp[9], mg[9];
        quat2mat(qp, mp);
        float qg[4] = {gt[b * 4 + 0], gt[b * 4 + 1], gt[b * 4 + 2], gt[b * 4 + 3]};
        quat2mat(qg, mg);
        #pragma unroll
        for (int i = 0; i < 9; i++) g_M[b * 9 + i] = mp[i] - mg[i];
    }
}

// ---------------------------------------------------------------------------
// Kernel 2: one CTA per batch; 3-stage cp.async pipeline staging 1024-point
// (12 KB) chunks. Per-point || p . (rm_pred - rm_gt) ||, sqrt on FMA pipe.
// Last-finished block does the deterministic final reduction.
// ---------------------------------------------------------------------------
#define PCHUNK 1024
#define PNCH   (PDIM / PCHUNK)     // 4 chunks
#define PNST   3                   // stages

__global__ __launch_bounds__(256) void k_point(const float* __restrict__ point,
                                               float* __restrict__ out) {
    const int b = blockIdx.x;
    const int t = threadIdx.x;

    __shared__ float sp[PNST][PCHUNK * 3];   // 36 KB
    __shared__ float Ms[9];
    __shared__ float red[8];
    __shared__ int isLast;

    const float4* __restrict__ gp = (const float4*)(point + (size_t)b * PDIM * 3);

    auto issue = [&](int c, int st) {
        unsigned dp = smem_u32(&sp[st][0]);
        const float4* src = gp + c * (PCHUNK * 3 / 4);   // 768 float4 per chunk
        cpa16(dp + t * 16,         src + t);
        cpa16(dp + (t + 256) * 16, src + t + 256);
        cpa16(dp + (t + 512) * 16, src + t + 512);
        cpa_commit();
    };

    issue(0, 0); issue(1, 1);

    if (t < 9) Ms[t] = g_M[b * 9 + t];
    __syncthreads();   // Ms visible before first consume
    const float M0 = Ms[0], M1 = Ms[1], M2 = Ms[2];
    const float M3 = Ms[3], M4 = Ms[4], M5 = Ms[5];
    const float M6 = Ms[6], M7 = Ms[7], M8 = Ms[8];

    float acc = 0.f;
    #pragma unroll
    for (int c = 0; c < PNCH; c++) {
        if (c < PNCH - 1) cpa_wait<1>();
        else              cpa_wait<0>();
        __syncthreads();

        const int st = (c < PNST) ? c : c - PNST;   // 0,1,2,0 for PNCH=4
        const float4* p4 = (const float4*)&sp[st][0];
        float4 v0 = p4[3 * t + 0];
        float4 v1 = p4[3 * t + 1];
        float4 v2 = p4[3 * t + 2];
        float px[4] = {v0.x, v0.w, v1.z, v2.y};
        float py[4] = {v0.y, v1.x, v1.w, v2.z};
        float pz[4] = {v0.z, v1.y, v2.x, v2.w};
        #pragma unroll
        for (int r = 0; r < 4; r++) {
            float x = px[r], y = py[r], z = pz[r];
            float dx = x * M0 + y * M3 + z * M6;
            float dy = x * M1 + y * M4 + z * M7;
            float dz = x * M2 + y * M5 + z * M8;
            acc += fsqrt_fma(dx * dx + dy * dy + dz * dz);
        }
        __syncthreads();
        if (c + 2 < PNCH) issue(c + 2, c + 2 < PNST ? c + 2 : c + 2 - PNST);
    }

    acc = warpSum(acc);
    if ((t & 31) == 0) red[t >> 5] = acc;
    __syncthreads();
    if (t < 32) {
        float x = (t < 8) ? red[t] : 0.f;
        x = warpSum(x);
        if (t == 0) g_part[b] = x;
    }

    // Last-block-done final reduction (deterministic fixed-order sum).
    if (t == 0) {
        __threadfence();
        unsigned int prev = atomicAdd(&g_cnt, 1u);
        isLast = (prev == (unsigned)(BDIM - 1));
    }
    __syncthreads();
    if (isLast) {
        float sfin = g_part[t] + g_part[t + 256];
        sfin = warpSum(sfin);
        if ((t & 31) == 0) red[t >> 5] = sfin;
        __syncthreads();
        if (t < 32) {
            float x = (t < 8) ? red[t] : 0.f;
            x = warpSum(x);
            if (t == 0) {
                out[0] = x * (1.0f / ((float)BDIM * (float)PDIM));
                g_cnt = 0u;   // reset for next graph replay
            }
        }
    }
}

extern "C" void kernel_launch(void* const* d_in, const int* in_sizes, int n_in,
                              void* d_out, int out_size) {
    const float* s     = (const float*)d_in[0];  // softEncodePred (B,K)
    const float* q     = (const float*)d_in[1];  // oriHistogramMap (B,K,4)
    const float* gt    = (const float*)d_in[2];  // gt (B,4)
    const float* point = (const float*)d_in[3];  // point (B,P,3)
    float* out = (float*)d_out;

    k_accum<<<BDIM, 256>>>(s, q, gt);
    k_point<<<BDIM, 256>>>(point, out);
}

// round 7
// speedup vs baseline: 1.3022x; 1.0472x over previous
#include <cuda_runtime.h>
#include <math.h>

#define KDIM 8192
#define BDIM 512
#define PDIM 4096

#define ACHUNK 512
#define ANCH   (KDIM / ACHUNK)     // 16 accum chunks
#define ANST   3                   // accum stages
#define PCHUNK 1024
#define PNCH   (PDIM / PCHUNK)     // 4 point chunks (768 float4 each)

// Scratch (allocation-free rule: __device__ globals)
__device__ float g_part[BDIM];       // per-block point partial sums
__device__ unsigned int g_cnt;       // last-block-done counter (self-reset)

__device__ __forceinline__ float warpSum(float v) {
    #pragma unroll
    for (int o = 16; o; o >>= 1) v += __shfl_xor_sync(0xffffffffu, v, o);
    return v;
}

// cp.async helpers (16B, cache-global)
__device__ __forceinline__ void cpa16(unsigned dst, const void* src) {
    asm volatile("cp.async.cg.shared.global [%0], [%1], 16;" :: "r"(dst), "l"(src));
}
__device__ __forceinline__ void cpa_commit() {
    asm volatile("cp.async.commit_group;");
}
template <int N>
__device__ __forceinline__ void cpa_wait() {
    asm volatile("cp.async.wait_group %0;" :: "n"(N));
}
__device__ __forceinline__ unsigned smem_u32(const void* p) {
    return (unsigned)__cvta_generic_to_shared(p);
}

// FMA/ALU-pipe exp (no MUFU). |x| <= ~20, rel err ~1.5e-7.
__device__ __forceinline__ float fexp(float x) {
    float t  = x * 1.4426950408889634f;
    float fn = t + 12582912.0f;
    int   n  = __float_as_int(fn) - 0x4B400000;
    float r  = t - (fn - 12582912.0f);
    float p = 1.5403530393e-4f;
    p = fmaf(p, r, 1.3333558146e-3f);
    p = fmaf(p, r, 9.6181291076e-3f);
    p = fmaf(p, r, 5.5504108665e-2f);
    p = fmaf(p, r, 2.4022650696e-1f);
    p = fmaf(p, r, 6.9314718056e-1f);
    p = fmaf(p, r, 1.0f);
    return __int_as_float(__float_as_int(p) + (n << 23));
}

// FMA/ALU-pipe sqrt: magic rsqrt + 2 Newton iters, then c * rsqrt(c).
__device__ __forceinline__ float fsqrt_fma(float c) {
    float y = __int_as_float(0x5f3759df - (__float_as_int(c) >> 1));
    float h = 0.5f * c;
    y = y * fmaf(-h * y, y, 1.5f);
    y = y * fmaf(-h * y, y, 1.5f);
    return c * y;
}

__device__ __forceinline__ void quat2mat(const float qv[4], float mm[9]) {
    float r = qv[0], i = qv[1], j = qv[2], k = qv[3];
    float two_s = __fdividef(2.0f, r * r + i * i + j * j + k * k);
    mm[0] = 1.0f - two_s * (j * j + k * k);
    mm[1] = two_s * (i * j - k * r);
    mm[2] = two_s * (i * k + j * r);
    mm[3] = two_s * (i * j + k * r);
    mm[4] = 1.0f - two_s * (i * i + k * k);
    mm[5] = two_s * (j * k - i * r);
    mm[6] = two_s * (i * k - j * r);
    mm[7] = two_s * (j * k + i * r);
    mm[8] = 1.0f - two_s * (i * i + j * j);
}

// ---------------------------------------------------------------------------
// One fused kernel, one CTA per batch.
// cp.async group commit order: P0, A0..A15, P1, P2, P3 (retire in order).
// Accum-loop wait accounting (issue of A_{c+3} happens AFTER the consume
// barrier): committed before wait at iter c = {P0, A0..A_{c+2}} = c+4 groups;
// wait_group 2 retires the c+2 oldest = P0 and A0..A_c  ==> chunk c is safe.
// ---------------------------------------------------------------------------
__global__ __launch_bounds__(256) void k_fused(const float* __restrict__ s,
                                               const float* __restrict__ q,
                                               const float* __restrict__ gt,
                                               const float* __restrict__ point,
                                               float* __restrict__ out) {
    const int b = blockIdx.x;
    const int t = threadIdx.x;

    __shared__ float4 sq[ANST][ACHUNK];       // 24 KB q stages
    __shared__ float  ss[ANST][ACHUNK];       // 6 KB  s stages
    __shared__ float4 sp0[PCHUNK * 3 / 4];    // 12 KB point chunk buffer (768 float4)
    __shared__ float red[80];
    __shared__ float Ms[9];
    __shared__ int isLast;

    const float4* __restrict__ gq = (const float4*)(q + (size_t)b * KDIM * 4);
    const float4* __restrict__ gs = (const float4*)(s + (size_t)b * KDIM);
    const float4* __restrict__ gp = (const float4*)(point + (size_t)b * PDIM * 3);

    // Issue a 768-float4 point chunk into an smem region (3 cp.async / thread)
    auto issueP = [&](const float4* dstBase, int chunk) {
        unsigned d = smem_u32(dstBase);
        const float4* src = gp + chunk * 768;
        cpa16(d + t * 16,          src + t);
        cpa16(d + (t + 256) * 16,  src + t + 256);
        cpa16(d + (t + 512) * 16,  src + t + 512);
        cpa_commit();
    };
    // Issue accum chunk c into stage st (q: 2/thread, s: 1 for t<128)
    auto issueA = [&](int c, int st) {
        unsigned dq = smem_u32(&sq[st][0]);
        const float4* srcq = gq + c * ACHUNK;
        cpa16(dq + t * 16,         srcq + t);
        cpa16(dq + (t + 256) * 16, srcq + t + 256);
        if (t < 128) {
            unsigned ds = smem_u32(&ss[st][0]);
            cpa16(ds + t * 16, gs + c * (ACHUNK / 4) + t);
        }
        cpa_commit();
    };

    // Pre-issue: P0 (hides under accum stream), then 3 accum chunks.
    issueP(sp0, 0);
    issueA(0, 0);
    issueA(1, 1);
    issueA(2, 2);

    float a0 = 0.f, a1 = 0.f, a2 = 0.f, a3 = 0.f, a4 = 0.f;
    float a5 = 0.f, a6 = 0.f, a7 = 0.f, a8 = 0.f, a9 = 0.f;

    #pragma unroll 4
    for (int c = 0; c < ANCH; c++) {
        if (c < ANCH - 2)       cpa_wait<2>();   // retires P0 and A0..A_c
        else if (c == ANCH - 2) cpa_wait<1>();
        else                    cpa_wait<0>();
        __syncthreads();   // chunk c visible to all threads

        const int st = c % ANST;
        const float4* q4s = &sq[st][0];
        float4 qa = q4s[t];
        float4 qb = q4s[t + 256];
        float w0 = fexp(ss[st][t]);
        float w1 = fexp(ss[st][t + 256]);
        {
            float wr = w0 * qa.x, wi = w0 * qa.y, wj = w0 * qa.z, wk = w0 * qa.w;
            a0 += wr * qa.x; a1 += wr * qa.y; a2 += wr * qa.z; a3 += wr * qa.w;
            a4 += wi * qa.y; a5 += wi * qa.z; a6 += wi * qa.w;
            a7 += wj * qa.z; a8 += wj * qa.w; a9 += wk * qa.w;
        }
        {
            float wr = w1 * qb.x, wi = w1 * qb.y, wj = w1 * qb.z, wk = w1 * qb.w;
            a0 += wr * qb.x; a1 += wr * qb.y; a2 += wr * qb.z; a3 += wr * qb.w;
            a4 += wi * qb.y; a5 += wi * qb.z; a6 += wi * qb.w;
            a7 += wj * qb.z; a8 += wj * qb.w; a9 += wk * qb.w;
        }
        __syncthreads();   // all threads done reading stage c%ANST
        if (c + 3 < ANCH) issueA(c + 3, (c + 3) % ANST);   // overwrites that stage
    }

    // Deterministic block reduction of the 10 accumulators.
    float acc[10] = {a0, a1, a2, a3, a4, a5, a6, a7, a8, a9};
    #pragma unroll
    for (int i = 0; i < 10; i++) acc[i] = warpSum(acc[i]);
    const int w = t >> 5, l = t & 31;
    if (l == 0) {
        #pragma unroll
        for (int i = 0; i < 10; i++) red[w * 10 + i] = acc[i];
    }
    __syncthreads();   // red ready; all threads done with sq/ss

    // Reuse the 24 KB sq region as point chunk buffers 1 and 2.
    float4* sp1 = &sq[0][0];
    float4* sp2 = &sq[0][0] + 768;
    issueP(sp1, 1);    // P1
    issueP(sp2, 2);    // P2

    // Thread 0: finish A, Jacobi eig, quat->mat difference -> Ms
    // (runs while P1/P2 cp.asyncs are in flight).
    if (t == 0) {
        float A[10];
        #pragma unroll
        for (int i = 0; i < 10; i++) {
            float sA = 0.f;
            #pragma unroll
            for (int w2 = 0; w2 < 8; w2++) sA += red[w2 * 10 + i];
            A[i] = sA;
        }

        float a[4][4], v[4][4];
        a[0][0] = A[0];
        a[0][1] = a[1][0] = A[1];
        a[0][2] = a[2][0] = A[2];
        a[0][3] = a[3][0] = A[3];
        a[1][1] = A[4];
        a[1][2] = a[2][1] = A[5];
        a[1][3] = a[3][1] = A[6];
        a[2][2] = A[7];
        a[2][3] = a[3][2] = A[8];
        a[3][3] = A[9];
        #pragma unroll
        for (int i = 0; i < 4; i++)
            #pragma unroll
            for (int j = 0; j < 4; j++) v[i][j] = (i == j) ? 1.0f : 0.0f;

        const int PP[6] = {0, 0, 0, 1, 1, 2};
        const int QQ[6] = {1, 2, 3, 2, 3, 3};

        for (int sweep = 0; sweep < 6; sweep++) {
            #pragma unroll
            for (int pair = 0; pair < 6; pair++) {
                int p = PP[pair], qi = QQ[pair];
                float apq = a[p][qi];
                if (fabsf(apq) > 1e-30f) {
                    float theta = __fdividef(a[qi][qi] - a[p][p], 2.0f * apq);
                    float tt = __fdividef(1.0f, fabsf(theta) + sqrtf(theta * theta + 1.0f));
                    if (theta < 0.0f) tt = -tt;
                    float c = rsqrtf(tt * tt + 1.0f);
                    float sn = tt * c;
                    float app = a[p][p], aqq = a[qi][qi];
                    a[p][p] = app - tt * apq;
                    a[qi][qi] = aqq + tt * apq;
                    a[p][qi] = a[qi][p] = 0.0f;
                    #pragma unroll
                    for (int r = 0; r < 4; r++) {
                        if (r != p && r != qi) {
                            float arp = a[r][p], arq = a[r][qi];
                            a[r][p] = a[p][r] = c * arp - sn * arq;
                            a[r][qi] = a[qi][r] = sn * arp + c * arq;
                        }
                    }
                    #pragma unroll
                    for (int r = 0; r < 4; r++) {
                        float vrp = v[r][p], vrq = v[r][qi];
                        v[r][p] = c * vrp - sn * vrq;
                        v[r][qi] = sn * vrp + c * vrq;
                    }
                }
            }
        }

        int best = 0;
        float bv = a[0][0];
        #pragma unroll
        for (int i = 1; i < 4; i++)
            if (a[i][i] > bv) { bv = a[i][i]; best = i; }

        float qp[4] = {v[0][best], v[1][best], v[2][best], v[3][best]};
        // sign/norm of qp irrelevant: quat2mat divides by |q|^2 and is even in q
        float mp[9], mg[9];
        quat2mat(qp, mp);
        float qg[4] = {gt[b * 4 + 0], gt[b * 4 + 1], gt[b * 4 + 2], gt[b * 4 + 3]};
        quat2mat(qg, mg);
        #pragma unroll
        for (int i = 0; i < 9; i++) Ms[i] = mp[i] - mg[i];
    }
    __syncthreads();   // Ms visible; P1/P2 committed by all threads
    const float M0 = Ms[0], M1 = Ms[1], M2 = Ms[2];
    const float M3 = Ms[3], M4 = Ms[4], M5 = Ms[5];
    const float M6 = Ms[6], M7 = Ms[7], M8 = Ms[8];

    // Consume one 1024-point chunk from an smem region.
    float pacc = 0.f;
    auto consumeP = [&](const float4* P) {
        float4 v0 = P[3 * t + 0];
        float4 v1 = P[3 * t + 1];
        float4 v2 = P[3 * t + 2];
        float px[4] = {v0.x, v0.w, v1.z, v2.y};
        float py[4] = {v0.y, v1.x, v1.w, v2.z};
        float pz[4] = {v0.z, v1.y, v2.x, v2.w};
        #pragma unroll
        for (int r = 0; r < 4; r++) {
            float x = px[r], y = py[r], z = pz[r];
            float dx = x * M0 + y * M3 + z * M6;
            float dy = x * M1 + y * M4 + z * M7;
            float dz = x * M2 + y * M5 + z * M8;
            pacc += fsqrt_fma(dx * dx + dy * dy + dz * dz);
        }
    };

    // P0 retired (older than A15, which drained at wait<0>).
    consumeP(sp0);             // chunk 0
    __syncthreads();           // all threads done reading sp0
    issueP(sp0, 3);            // P3 reuses sp0
    cpa_wait<2>();             // pending <= 2 of {P1,P2,P3} => P1 done
    __syncthreads();
    consumeP(sp1);             // chunk 1
    cpa_wait<1>();             // P2 done
    __syncthreads();
    consumeP(sp2);             // chunk 2
    cpa_wait<0>();             // P3 done
    __syncthreads();
    consumeP(sp0);             // chunk 3

    // Block reduction of point sum.
    pacc = warpSum(pacc);
    if (l == 0) red[w] = pacc;
    __syncthreads();
    if (t < 32) {
        float x = (t < 8) ? red[t] : 0.f;
        x = warpSum(x);
        if (t == 0) g_part[b] = x;
    }

    // Last-block-done final reduction (deterministic fixed-order sum).
    if (t == 0) {
        __threadfence();
        unsigned int prev = atomicAdd(&g_cnt, 1u);
        isLast = (prev == (unsigned)(BDIM - 1));
    }
    __syncthreads();
    if (isLast) {
        float sfin = g_part[t] + g_part[t + 256];
        sfin = warpSum(sfin);
        if ((t & 31) == 0) red[t >> 5] = sfin;
        __syncthreads();
        if (t < 32) {
            float x = (t < 8) ? red[t] : 0.f;
            x = warpSum(x);
            if (t == 0) {
                out[0] = x * (1.0f / ((float)BDIM * (float)PDIM));
                g_cnt = 0u;   // reset for next graph replay
            }
        }
    }
}

extern "C" void kernel_launch(void* const* d_in, const int* in_sizes, int n_in,
                              void* d_out, int out_size) {
    const float* s     = (const float*)d_in[0];  // softEncodePred (B,K)
    const float* q     = (const float*)d_in[1];  // oriHistogramMap (B,K,4)
    const float* gt    = (const float*)d_in[2];  // gt (B,4)
    const float* point = (const float*)d_in[3];  // point (B,P,3)
    float* out = (float*)d_out;

    k_fused<<<BDIM, 256>>>(s, q, gt, point, out);
}